// round 1
// baseline (speedup 1.0000x reference)
#include <cuda_runtime.h>

#define NB 26
#define POSE_F 78        // 26*3 floats per pose
#define TPB 128
#define BATCH 131072

struct M3 { float a[9]; };
struct V3 { float v[3]; };

// Full bone step: abs_loc + rotation chain update.
// Ap/bp passed BY VALUE so Ao/bo may alias the caller's current state.
__device__ __forceinline__ void fullstep(int bone, M3 Ap, V3 bp, M3& Ao, V3& bo,
                                         float* __restrict__ P,
                                         const float* __restrict__ rr5,
                                         const float* __restrict__ rl)
{
    const float lx = rl[bone * 3 + 0];
    const float ly = rl[bone * 3 + 1];
    const float lz = rl[bone * 3 + 2];

    // abs_loc[bone] = l . Ap + bp   (row-vector times matrix)
    float ax = lx * Ap.a[0] + ly * Ap.a[3] + lz * Ap.a[6] + bp.v[0];
    float ay = lx * Ap.a[1] + ly * Ap.a[4] + lz * Ap.a[7] + bp.v[1];
    float az = lx * Ap.a[2] + ly * Ap.a[5] + lz * Ap.a[8] + bp.v[2];

    // read this bone's euler angles, then overwrite the slot with abs_loc (in-place)
    float ez = P[bone * 3 + 0];
    float ey = P[bone * 3 + 1];
    float ex = P[bone * 3 + 2];
    P[bone * 3 + 0] = ax;
    P[bone * 3 + 1] = ay;
    P[bone * 3 + 2] = az;

    float sz, cz, sy, cy, sx, cx;
    __sincosf(ez, &sz, &cz);
    __sincosf(ey, &sy, &cy);
    __sincosf(ex, &sx, &cx);

    // Only 5 entries of M = R_ref (*) R_chg are needed by matrix_to_euler:
    // m00 = cz*cy, m10 = sz*cy, m20 = -sy, m21 = cy*sx, m22 = cy*cx
    const float* r = rr5 + bone * 5;
    float M00 = r[0] * (cz * cy);
    float M10 = r[1] * (sz * cy);
    float M20 = r[2] * (-sy);
    float M21 = r[3] * (cy * sx);
    float M22 = r[4] * (cy * cx);

    // Trig-free euler->matrix rebuild:
    // z = atan2(M10, M00)  ->  cos = M00/h, sin = M10/h
    // y = asin(-M20)       ->  sin = -M20,  cos = sqrt(1 - sin^2) (>= 0)
    // x = atan2(M21, M22)  ->  cos = M22/h, sin = M21/h
    float i0 = rsqrtf(fmaxf(M00 * M00 + M10 * M10, 1e-30f));
    float CZ = M00 * i0, SZ = M10 * i0;
    float SY = -M20;
    float CY = sqrtf(fmaxf(1.0f - SY * SY, 0.0f));
    float i2 = rsqrtf(fmaxf(M21 * M21 + M22 * M22, 1e-30f));
    float CX = M22 * i2, SX = M21 * i2;

    // Rebuilt rotation R (ZYX euler)
    float R00 = CZ * CY;
    float R01 = CZ * SY * SX - SZ * CX;
    float R02 = CZ * SY * CX + SZ * SX;
    float R10 = SZ * CY;
    float R11 = SZ * SY * SX + CZ * CX;
    float R12 = SZ * SY * CX - CZ * SX;
    float R20 = -SY;
    float R21 = CY * SX;
    float R22 = CY * CX;

    // A_new = Ap @ R
    M3 T;
    #pragma unroll
    for (int k = 0; k < 3; k++) {
        float a0 = Ap.a[3 * k + 0], a1 = Ap.a[3 * k + 1], a2 = Ap.a[3 * k + 2];
        T.a[3 * k + 0] = a0 * R00 + a1 * R10 + a2 * R20;
        T.a[3 * k + 1] = a0 * R01 + a1 * R11 + a2 * R21;
        T.a[3 * k + 2] = a0 * R02 + a1 * R12 + a2 * R22;
    }
    // b_new = (bp + l) . R
    float tx = bp.v[0] + lx, ty = bp.v[1] + ly, tz = bp.v[2] + lz;
    V3 tb;
    tb.v[0] = tx * R00 + ty * R10 + tz * R20;
    tb.v[1] = tx * R01 + ty * R11 + tz * R21;
    tb.v[2] = tx * R02 + ty * R12 + tz * R22;

    Ao = T;
    bo = tb;
}

// Leaf bone: only abs_loc needed (its rotation is never consumed).
__device__ __forceinline__ void leafstep(int bone, const M3& Ap, const V3& bp,
                                         float* __restrict__ P,
                                         const float* __restrict__ rl)
{
    const float lx = rl[bone * 3 + 0];
    const float ly = rl[bone * 3 + 1];
    const float lz = rl[bone * 3 + 2];
    P[bone * 3 + 0] = lx * Ap.a[0] + ly * Ap.a[3] + lz * Ap.a[6] + bp.v[0];
    P[bone * 3 + 1] = lx * Ap.a[1] + ly * Ap.a[4] + lz * Ap.a[7] + bp.v[1];
    P[bone * 3 + 2] = lx * Ap.a[2] + ly * Ap.a[5] + lz * Ap.a[8] + bp.v[2];
}

__global__ void __launch_bounds__(TPB)
fk_kernel(const float* __restrict__ x,
          const float* __restrict__ rel_loc,
          const float* __restrict__ rel_rot_ref,
          float* __restrict__ out)
{
    __shared__ float pose[TPB * POSE_F];   // in-place: angles in, abs_loc out
    __shared__ float rr5[NB * 5];          // 5 needed entries of R_ref per bone
    __shared__ float rl[NB * 3];           // rel_loc

    const int tid = threadIdx.x;

    // Per-block precompute of reference-rotation entries (26 threads, accurate trig)
    if (tid < NB) {
        float ez = rel_rot_ref[tid * 3 + 0];
        float ey = rel_rot_ref[tid * 3 + 1];
        float ex = rel_rot_ref[tid * 3 + 2];
        float sz, cz, sy, cy, sx, cx;
        sincosf(ez, &sz, &cz);
        sincosf(ey, &sy, &cy);
        sincosf(ex, &sx, &cx);
        rr5[tid * 5 + 0] = cz * cy;   // m00
        rr5[tid * 5 + 1] = sz * cy;   // m10
        rr5[tid * 5 + 2] = -sy;       // m20
        rr5[tid * 5 + 3] = cy * sx;   // m21
        rr5[tid * 5 + 4] = cy * cx;   // m22
        rl[tid * 3 + 0] = rel_loc[tid * 3 + 0];
        rl[tid * 3 + 1] = rel_loc[tid * 3 + 1];
        rl[tid * 3 + 2] = rel_loc[tid * 3 + 2];
    }

    // Coalesced float4 staging of this block's 128 poses
    const int NV4 = TPB * POSE_F / 4;  // 2496
    const float4* gin = reinterpret_cast<const float4*>(x) + (size_t)blockIdx.x * NV4;
    float4* sp4 = reinterpret_cast<float4*>(pose);
    for (int i = tid; i < NV4; i += TPB) sp4[i] = gin[i];
    __syncthreads();

    float* P = pose + tid * POSE_F;

    M3 A, A1, A4, A6;
    V3 b, b1, b4, b6;

    // bone 0 (root): Ap = I, bp = 0
    {
        M3 I; V3 z;
        I.a[0] = 1.f; I.a[1] = 0.f; I.a[2] = 0.f;
        I.a[3] = 0.f; I.a[4] = 1.f; I.a[5] = 0.f;
        I.a[6] = 0.f; I.a[7] = 0.f; I.a[8] = 1.f;
        z.v[0] = 0.f; z.v[1] = 0.f; z.v[2] = 0.f;
        fullstep(0, I, z, A, b, P, rr5, rl);
    }
    // spine: 0 -> 1 -> 2 -> 3 -> 4 -> 5 -> 6
    fullstep(1, A, b, A, b, P, rr5, rl);  A1 = A; b1 = b;
    fullstep(2, A, b, A, b, P, rr5, rl);
    fullstep(3, A, b, A, b, P, rr5, rl);
    fullstep(4, A, b, A, b, P, rr5, rl);  A4 = A; b4 = b;
    fullstep(5, A, b, A, b, P, rr5, rl);
    fullstep(6, A, b, A, b, P, rr5, rl);  A6 = A; b6 = b;
    // head leaves off bone 6
    leafstep(23, A6, b6, P, rl);
    leafstep(24, A6, b6, P, rl);
    leafstep(25, A6, b6, P, rl);
    // chain 7 -> 8 -> 9 -> (10 leaf), rooted at 4
    fullstep(7, A4, b4, A, b, P, rr5, rl);
    fullstep(8, A, b, A, b, P, rr5, rl);
    fullstep(9, A, b, A, b, P, rr5, rl);
    leafstep(10, A, b, P, rl);
    // chain 11 -> 12 -> 13 -> (14 leaf), rooted at 4
    fullstep(11, A4, b4, A, b, P, rr5, rl);
    fullstep(12, A, b, A, b, P, rr5, rl);
    fullstep(13, A, b, A, b, P, rr5, rl);
    leafstep(14, A, b, P, rl);
    // chain 15 -> 16 -> 17 -> (18 leaf), rooted at 1
    fullstep(15, A1, b1, A, b, P, rr5, rl);
    fullstep(16, A, b, A, b, P, rr5, rl);
    fullstep(17, A, b, A, b, P, rr5, rl);
    leafstep(18, A, b, P, rl);
    // chain 19 -> 20 -> 21 -> (22 leaf), rooted at 1
    fullstep(19, A1, b1, A, b, P, rr5, rl);
    fullstep(20, A, b, A, b, P, rr5, rl);
    fullstep(21, A, b, A, b, P, rr5, rl);
    leafstep(22, A, b, P, rl);

    __syncthreads();

    // Coalesced float4 write-back
    float4* gout = reinterpret_cast<float4*>(out) + (size_t)blockIdx.x * NV4;
    for (int i = tid; i < NV4; i += TPB) gout[i] = sp4[i];
}

extern "C" void kernel_launch(void* const* d_in, const int* in_sizes, int n_in,
                              void* d_out, int out_size)
{
    const float* x           = (const float*)d_in[0];  // (131072, 26, 3)
    const float* rel_loc     = (const float*)d_in[1];  // (26, 3)
    const float* rel_rot_ref = (const float*)d_in[2];  // (26, 3)
    float* out               = (float*)d_out;          // (131072, 26, 3)

    const int batch = in_sizes[0] / POSE_F;            // 131072
    fk_kernel<<<batch / TPB, TPB>>>(x, rel_loc, rel_rot_ref, out);
}

// round 3
// speedup vs baseline: 1.2681x; 1.2681x over previous
#include <cuda_runtime.h>

#define NB 26
#define POSE_F 78        // 26*3 floats per pose
#define TPB 64
#define BATCH 131072

// Precomputed reference-rotation entries (5 per bone) live here,
// filled by a tiny pre-kernel each launch (graph-capturable, deterministic).
__device__ float g_rr5[NB * 5];

struct M3 { float a[9]; };
struct V3 { float v[3]; };

// approx sqrt: t * rsqrt(t), safe near 0 after clamping
__device__ __forceinline__ float fsqrt_approx(float t) {
    t = fmaxf(t, 1e-30f);
    return t * rsqrtf(t);
}

// Full bone step: abs_loc + rotation chain update.
// Ap/bp passed BY VALUE so Ao/bo may alias the caller's current state.
__device__ __forceinline__ void fullstep(int bone, M3 Ap, V3 bp, M3& Ao, V3& bo,
                                         float* __restrict__ P,
                                         const float* __restrict__ rr5,
                                         const float* __restrict__ rl)
{
    const float lx = rl[bone * 3 + 0];
    const float ly = rl[bone * 3 + 1];
    const float lz = rl[bone * 3 + 2];

    // abs_loc[bone] = l . Ap + bp   (row-vector times matrix)
    float ax = lx * Ap.a[0] + ly * Ap.a[3] + lz * Ap.a[6] + bp.v[0];
    float ay = lx * Ap.a[1] + ly * Ap.a[4] + lz * Ap.a[7] + bp.v[1];
    float az = lx * Ap.a[2] + ly * Ap.a[5] + lz * Ap.a[8] + bp.v[2];

    // read this bone's euler angles, then overwrite the slot with abs_loc (in-place)
    float ez = P[bone * 3 + 0];
    float ey = P[bone * 3 + 1];
    float ex = P[bone * 3 + 2];
    P[bone * 3 + 0] = ax;
    P[bone * 3 + 1] = ay;
    P[bone * 3 + 2] = az;

    float sz, cz, sy, cy, sx, cx;
    __sincosf(ez, &sz, &cz);
    __sincosf(ey, &sy, &cy);
    __sincosf(ex, &sx, &cx);

    // Only 5 entries of M = R_ref (hadamard) R_chg are needed by matrix_to_euler:
    // m00 = cz*cy, m10 = sz*cy, m20 = -sy, m21 = cy*sx, m22 = cy*cx
    const float* r = rr5 + bone * 5;
    float M00 = r[0] * (cz * cy);
    float M10 = r[1] * (sz * cy);
    float M20 = r[2] * (-sy);
    float M21 = r[3] * (cy * sx);
    float M22 = r[4] * (cy * cx);

    // Trig-free euler->matrix rebuild:
    // z = atan2(M10, M00)  ->  cos = M00/h, sin = M10/h
    // y = asin(-M20)       ->  sin = -M20,  cos = sqrt(1 - sin^2) (>= 0)
    // x = atan2(M21, M22)  ->  cos = M22/h, sin = M21/h
    float i0 = rsqrtf(fmaxf(M00 * M00 + M10 * M10, 1e-30f));
    float CZ = M00 * i0, SZ = M10 * i0;
    float SY = -M20;
    float CY = fsqrt_approx(1.0f - SY * SY);
    float i2 = rsqrtf(fmaxf(M21 * M21 + M22 * M22, 1e-30f));
    float CX = M22 * i2, SX = M21 * i2;

    // Rebuilt rotation R (ZYX euler)
    float R00 = CZ * CY;
    float R01 = CZ * SY * SX - SZ * CX;
    float R02 = CZ * SY * CX + SZ * SX;
    float R10 = SZ * CY;
    float R11 = SZ * SY * SX + CZ * CX;
    float R12 = SZ * SY * CX - CZ * SX;
    float R20 = -SY;
    float R21 = CY * SX;
    float R22 = CY * CX;

    // A_new = Ap @ R
    M3 T;
    #pragma unroll
    for (int k = 0; k < 3; k++) {
        float a0 = Ap.a[3 * k + 0], a1 = Ap.a[3 * k + 1], a2 = Ap.a[3 * k + 2];
        T.a[3 * k + 0] = a0 * R00 + a1 * R10 + a2 * R20;
        T.a[3 * k + 1] = a0 * R01 + a1 * R11 + a2 * R21;
        T.a[3 * k + 2] = a0 * R02 + a1 * R12 + a2 * R22;
    }
    // b_new = (bp + l) . R
    float tx = bp.v[0] + lx, ty = bp.v[1] + ly, tz = bp.v[2] + lz;
    V3 tb;
    tb.v[0] = tx * R00 + ty * R10 + tz * R20;
    tb.v[1] = tx * R01 + ty * R11 + tz * R21;
    tb.v[2] = tx * R02 + ty * R12 + tz * R22;

    Ao = T;
    bo = tb;
}

// Leaf bone: only abs_loc needed (its rotation is never consumed).
__device__ __forceinline__ void leafstep(int bone, const M3& Ap, const V3& bp,
                                         float* __restrict__ P,
                                         const float* __restrict__ rl)
{
    const float lx = rl[bone * 3 + 0];
    const float ly = rl[bone * 3 + 1];
    const float lz = rl[bone * 3 + 2];
    P[bone * 3 + 0] = lx * Ap.a[0] + ly * Ap.a[3] + lz * Ap.a[6] + bp.v[0];
    P[bone * 3 + 1] = lx * Ap.a[1] + ly * Ap.a[4] + lz * Ap.a[7] + bp.v[1];
    P[bone * 3 + 2] = lx * Ap.a[2] + ly * Ap.a[5] + lz * Ap.a[8] + bp.v[2];
}

// Tiny pre-kernel: accurate trig once, instead of per-block divergent sincosf.
__global__ void ref_table_kernel(const float* __restrict__ rel_rot_ref)
{
    int i = threadIdx.x;
    if (i < NB) {
        float ez = rel_rot_ref[i * 3 + 0];
        float ey = rel_rot_ref[i * 3 + 1];
        float ex = rel_rot_ref[i * 3 + 2];
        float sz, cz, sy, cy, sx, cx;
        sincosf(ez, &sz, &cz);
        sincosf(ey, &sy, &cy);
        sincosf(ex, &sx, &cx);
        g_rr5[i * 5 + 0] = cz * cy;   // m00
        g_rr5[i * 5 + 1] = sz * cy;   // m10
        g_rr5[i * 5 + 2] = -sy;       // m20
        g_rr5[i * 5 + 3] = cy * sx;   // m21
        g_rr5[i * 5 + 4] = cy * cx;   // m22
    }
}

__global__ void __launch_bounds__(TPB)
fk_kernel(const float* __restrict__ x,
          const float* __restrict__ rel_loc,
          float* __restrict__ out)
{
    __shared__ float pose[TPB * POSE_F];   // in-place: angles in, abs_loc out
    __shared__ float rr5[NB * 5];          // 5 needed entries of R_ref per bone
    __shared__ float rl[NB * 3];           // rel_loc

    const int tid = threadIdx.x;

    // Copy small tables (no trig here)
    if (tid < NB * 5) rr5[tid] = g_rr5[tid];
    if (tid + TPB < NB * 5) rr5[tid + TPB] = g_rr5[tid + TPB];
    if (tid + 2 * TPB < NB * 5) rr5[tid + 2 * TPB] = g_rr5[tid + 2 * TPB];
    if (tid < NB * 3) rl[tid] = rel_loc[tid];
    if (tid + TPB < NB * 3) rl[tid + TPB] = rel_loc[tid + TPB];

    // Coalesced float4 staging of this block's poses.
    // NV4 = 1248 = 19.5 * TPB  ->  20 iterations, last one predicated.
    const int NV4 = TPB * POSE_F / 4;                 // 1248
    const int NIT = (NV4 + TPB - 1) / TPB;            // 20
    const float4* gin = reinterpret_cast<const float4*>(x) + (size_t)blockIdx.x * NV4;
    float4* sp4 = reinterpret_cast<float4*>(pose);
    #pragma unroll
    for (int i = 0; i < NIT; i++) {
        int idx = tid + i * TPB;
        if (idx < NV4) sp4[idx] = gin[idx];
    }
    __syncthreads();

    float* P = pose + tid * POSE_F;

    M3 A, Asv;
    V3 b, bsv;

    // bone 0 (root): Ap = I, bp = 0 (constant-folded)
    {
        M3 I; V3 z;
        I.a[0] = 1.f; I.a[1] = 0.f; I.a[2] = 0.f;
        I.a[3] = 0.f; I.a[4] = 1.f; I.a[5] = 0.f;
        I.a[6] = 0.f; I.a[7] = 0.f; I.a[8] = 1.f;
        z.v[0] = 0.f; z.v[1] = 0.f; z.v[2] = 0.f;
        fullstep(0, I, z, A, b, P, rr5, rl);
    }
    fullstep(1, A, b, Asv, bsv, P, rr5, rl);   // Asv = A1

    // limbs rooted at bone 1 (done now so A1 needn't stay live later)
    fullstep(15, Asv, bsv, A, b, P, rr5, rl);
    fullstep(16, A, b, A, b, P, rr5, rl);
    fullstep(17, A, b, A, b, P, rr5, rl);
    leafstep(18, A, b, P, rl);
    fullstep(19, Asv, bsv, A, b, P, rr5, rl);
    fullstep(20, A, b, A, b, P, rr5, rl);
    fullstep(21, A, b, A, b, P, rr5, rl);
    leafstep(22, A, b, P, rl);

    // spine 2,3,4 (continue from A1)
    fullstep(2, Asv, bsv, A, b, P, rr5, rl);
    fullstep(3, A, b, A, b, P, rr5, rl);
    fullstep(4, A, b, Asv, bsv, P, rr5, rl);   // Asv = A4

    // limbs rooted at bone 4
    fullstep(7, Asv, bsv, A, b, P, rr5, rl);
    fullstep(8, A, b, A, b, P, rr5, rl);
    fullstep(9, A, b, A, b, P, rr5, rl);
    leafstep(10, A, b, P, rl);
    fullstep(11, Asv, bsv, A, b, P, rr5, rl);
    fullstep(12, A, b, A, b, P, rr5, rl);
    fullstep(13, A, b, A, b, P, rr5, rl);
    leafstep(14, A, b, P, rl);

    // spine 5,6 + head leaves
    fullstep(5, Asv, bsv, A, b, P, rr5, rl);
    fullstep(6, A, b, A, b, P, rr5, rl);
    leafstep(23, A, b, P, rl);
    leafstep(24, A, b, P, rl);
    leafstep(25, A, b, P, rl);

    __syncthreads();

    // Coalesced float4 write-back (same predicated tail)
    float4* gout = reinterpret_cast<float4*>(out) + (size_t)blockIdx.x * NV4;
    #pragma unroll
    for (int i = 0; i < NIT; i++) {
        int idx = tid + i * TPB;
        if (idx < NV4) gout[idx] = sp4[idx];
    }
}

extern "C" void kernel_launch(void* const* d_in, const int* in_sizes, int n_in,
                              void* d_out, int out_size)
{
    const float* x           = (const float*)d_in[0];  // (131072, 26, 3)
    const float* rel_loc     = (const float*)d_in[1];  // (26, 3)
    const float* rel_rot_ref = (const float*)d_in[2];  // (26, 3)
    float* out               = (float*)d_out;          // (131072, 26, 3)

    const int batch = in_sizes[0] / POSE_F;            // 131072
    ref_table_kernel<<<1, 32>>>(rel_rot_ref);
    fk_kernel<<<batch / TPB, TPB>>>(x, rel_loc, out);
}

// round 5
// speedup vs baseline: 1.2875x; 1.0153x over previous
#include <cuda_runtime.h>

#define NB 26
#define POSE_F 78        // 26*3 floats per pose
#define TPB 64
#define BATCH 131072

#define TAB_F (NB * 5 + NB * 3)   // 130 rr5 entries + 78 rel_loc = 208

// Staging global filled by the pre-kernel (rr5 then rl), then copied once
// into __constant__ via a stream-ordered D2D memcpy (graph-capturable node).
__device__ float g_tab[TAB_F];
__constant__ float c_tab[TAB_F];

#define C_RR5(i) c_tab[(i)]
#define C_RL(i)  c_tab[NB * 5 + (i)]

struct M3 { float a[9]; };
struct V3 { float v[3]; };

// approx sqrt: t * rsqrt(t), safe near 0 after clamping
__device__ __forceinline__ float fsqrt_approx(float t) {
    t = fmaxf(t, 1e-30f);
    return t * rsqrtf(t);
}

// Full bone step: abs_loc + rotation chain update.
// Ap/bp passed BY VALUE so Ao/bo may alias the caller's current state.
// bone is a compile-time literal at every call site -> LDC with immediate offset.
__device__ __forceinline__ void fullstep(int bone, M3 Ap, V3 bp, M3& Ao, V3& bo,
                                         float* __restrict__ P)
{
    const float lx = C_RL(bone * 3 + 0);
    const float ly = C_RL(bone * 3 + 1);
    const float lz = C_RL(bone * 3 + 2);

    // abs_loc[bone] = l . Ap + bp   (row-vector times matrix)
    float ax = lx * Ap.a[0] + ly * Ap.a[3] + lz * Ap.a[6] + bp.v[0];
    float ay = lx * Ap.a[1] + ly * Ap.a[4] + lz * Ap.a[7] + bp.v[1];
    float az = lx * Ap.a[2] + ly * Ap.a[5] + lz * Ap.a[8] + bp.v[2];

    // read this bone's euler angles, then overwrite the slot with abs_loc (in-place)
    float ez = P[bone * 3 + 0];
    float ey = P[bone * 3 + 1];
    float ex = P[bone * 3 + 2];
    P[bone * 3 + 0] = ax;
    P[bone * 3 + 1] = ay;
    P[bone * 3 + 2] = az;

    float sz, cz, sy, cy, sx, cx;
    __sincosf(ez, &sz, &cz);
    __sincosf(ey, &sy, &cy);
    __sincosf(ex, &sx, &cx);

    // Only 5 entries of M = R_ref (hadamard) R_chg are needed by matrix_to_euler:
    // m00 = cz*cy, m10 = sz*cy, m20 = -sy, m21 = cy*sx, m22 = cy*cx
    float M00 = C_RR5(bone * 5 + 0) * (cz * cy);
    float M10 = C_RR5(bone * 5 + 1) * (sz * cy);
    float M20 = C_RR5(bone * 5 + 2) * (-sy);
    float M21 = C_RR5(bone * 5 + 3) * (cy * sx);
    float M22 = C_RR5(bone * 5 + 4) * (cy * cx);

    // Trig-free euler->matrix rebuild:
    // z = atan2(M10, M00)  ->  cos = M00/h, sin = M10/h
    // y = asin(-M20)       ->  sin = -M20,  cos = sqrt(1 - sin^2) (>= 0)
    // x = atan2(M21, M22)  ->  cos = M22/h, sin = M21/h
    float i0 = rsqrtf(fmaxf(M00 * M00 + M10 * M10, 1e-30f));
    float CZ = M00 * i0, SZ = M10 * i0;
    float SY = -M20;
    float CY = fsqrt_approx(1.0f - SY * SY);
    float i2 = rsqrtf(fmaxf(M21 * M21 + M22 * M22, 1e-30f));
    float CX = M22 * i2, SX = M21 * i2;

    // Rebuilt rotation R (ZYX euler)
    float R00 = CZ * CY;
    float R01 = CZ * SY * SX - SZ * CX;
    float R02 = CZ * SY * CX + SZ * SX;
    float R10 = SZ * CY;
    float R11 = SZ * SY * SX + CZ * CX;
    float R12 = SZ * SY * CX - CZ * SX;
    float R20 = -SY;
    float R21 = CY * SX;
    float R22 = CY * CX;

    // A_new = Ap @ R
    M3 T;
    #pragma unroll
    for (int k = 0; k < 3; k++) {
        float a0 = Ap.a[3 * k + 0], a1 = Ap.a[3 * k + 1], a2 = Ap.a[3 * k + 2];
        T.a[3 * k + 0] = a0 * R00 + a1 * R10 + a2 * R20;
        T.a[3 * k + 1] = a0 * R01 + a1 * R11 + a2 * R21;
        T.a[3 * k + 2] = a0 * R02 + a1 * R12 + a2 * R22;
    }
    // b_new = (bp + l) . R
    float tx = bp.v[0] + lx, ty = bp.v[1] + ly, tz = bp.v[2] + lz;
    V3 tb;
    tb.v[0] = tx * R00 + ty * R10 + tz * R20;
    tb.v[1] = tx * R01 + ty * R11 + tz * R21;
    tb.v[2] = tx * R02 + ty * R12 + tz * R22;

    Ao = T;
    bo = tb;
}

// Leaf bone: only abs_loc needed (its rotation is never consumed).
__device__ __forceinline__ void leafstep(int bone, const M3& Ap, const V3& bp,
                                         float* __restrict__ P)
{
    const float lx = C_RL(bone * 3 + 0);
    const float ly = C_RL(bone * 3 + 1);
    const float lz = C_RL(bone * 3 + 2);
    P[bone * 3 + 0] = lx * Ap.a[0] + ly * Ap.a[3] + lz * Ap.a[6] + bp.v[0];
    P[bone * 3 + 1] = lx * Ap.a[1] + ly * Ap.a[4] + lz * Ap.a[7] + bp.v[1];
    P[bone * 3 + 2] = lx * Ap.a[2] + ly * Ap.a[5] + lz * Ap.a[8] + bp.v[2];
}

// Tiny pre-kernel: accurate trig once for the 26 reference rotations,
// plus copy rel_loc, all into one staging table.
__global__ void ref_table_kernel(const float* __restrict__ rel_rot_ref,
                                 const float* __restrict__ rel_loc)
{
    int i = threadIdx.x;
    if (i < NB) {
        float ez = rel_rot_ref[i * 3 + 0];
        float ey = rel_rot_ref[i * 3 + 1];
        float ex = rel_rot_ref[i * 3 + 2];
        float sz, cz, sy, cy, sx, cx;
        sincosf(ez, &sz, &cz);
        sincosf(ey, &sy, &cy);
        sincosf(ex, &sx, &cx);
        g_tab[i * 5 + 0] = cz * cy;   // m00
        g_tab[i * 5 + 1] = sz * cy;   // m10
        g_tab[i * 5 + 2] = -sy;       // m20
        g_tab[i * 5 + 3] = cy * sx;   // m21
        g_tab[i * 5 + 4] = cy * cx;   // m22
    }
    for (int j = i; j < NB * 3; j += blockDim.x)
        g_tab[NB * 5 + j] = rel_loc[j];
}

__global__ void __launch_bounds__(TPB, 11)
fk_kernel(const float* __restrict__ x,
          float* __restrict__ out)
{
    __shared__ float pose[TPB * POSE_F];   // in-place: angles in, abs_loc out

    const int tid = threadIdx.x;

    // Coalesced float4 staging of this block's poses.
    // NV4 = 1248 = 19.5 * TPB  ->  20 iterations, last one predicated.
    const int NV4 = TPB * POSE_F / 4;                 // 1248
    const int NIT = (NV4 + TPB - 1) / TPB;            // 20
    const float4* gin = reinterpret_cast<const float4*>(x) + (size_t)blockIdx.x * NV4;
    float4* sp4 = reinterpret_cast<float4*>(pose);
    #pragma unroll
    for (int i = 0; i < NIT; i++) {
        int idx = tid + i * TPB;
        if (idx < NV4) sp4[idx] = gin[idx];
    }
    __syncthreads();

    float* P = pose + tid * POSE_F;

    M3 A, Asv;
    V3 b, bsv;

    // bone 0 (root): Ap = I, bp = 0 (constant-folded)
    {
        M3 I; V3 z;
        I.a[0] = 1.f; I.a[1] = 0.f; I.a[2] = 0.f;
        I.a[3] = 0.f; I.a[4] = 1.f; I.a[5] = 0.f;
        I.a[6] = 0.f; I.a[7] = 0.f; I.a[8] = 1.f;
        z.v[0] = 0.f; z.v[1] = 0.f; z.v[2] = 0.f;
        fullstep(0, I, z, A, b, P);
    }
    fullstep(1, A, b, Asv, bsv, P);   // Asv = A1

    // limbs rooted at bone 1 (done now so A1 needn't stay live later)
    fullstep(15, Asv, bsv, A, b, P);
    fullstep(16, A, b, A, b, P);
    fullstep(17, A, b, A, b, P);
    leafstep(18, A, b, P);
    fullstep(19, Asv, bsv, A, b, P);
    fullstep(20, A, b, A, b, P);
    fullstep(21, A, b, A, b, P);
    leafstep(22, A, b, P);

    // spine 2,3,4 (continue from A1)
    fullstep(2, Asv, bsv, A, b, P);
    fullstep(3, A, b, A, b, P);
    fullstep(4, A, b, Asv, bsv, P);   // Asv = A4

    // limbs rooted at bone 4
    fullstep(7, Asv, bsv, A, b, P);
    fullstep(8, A, b, A, b, P);
    fullstep(9, A, b, A, b, P);
    leafstep(10, A, b, P);
    fullstep(11, Asv, bsv, A, b, P);
    fullstep(12, A, b, A, b, P);
    fullstep(13, A, b, A, b, P);
    leafstep(14, A, b, P);

    // spine 5,6 + head leaves
    fullstep(5, Asv, bsv, A, b, P);
    fullstep(6, A, b, A, b, P);
    leafstep(23, A, b, P);
    leafstep(24, A, b, P);
    leafstep(25, A, b, P);

    __syncthreads();

    // Coalesced float4 write-back (same predicated tail)
    float4* gout = reinterpret_cast<float4*>(out) + (size_t)blockIdx.x * NV4;
    #pragma unroll
    for (int i = 0; i < NIT; i++) {
        int idx = tid + i * TPB;
        if (idx < NV4) gout[idx] = sp4[idx];
    }
}

extern "C" void kernel_launch(void* const* d_in, const int* in_sizes, int n_in,
                              void* d_out, int out_size)
{
    const float* x           = (const float*)d_in[0];  // (131072, 26, 3)
    const float* rel_loc     = (const float*)d_in[1];  // (26, 3)
    const float* rel_rot_ref = (const float*)d_in[2];  // (26, 3)
    float* out               = (float*)d_out;          // (131072, 26, 3)

    const int batch = in_sizes[0] / POSE_F;            // 131072

    // 1) accurate trig for the 26 reference rotations + rel_loc -> g_tab
    ref_table_kernel<<<1, 128>>>(rel_rot_ref, rel_loc);

    // 2) one stream-ordered D2D copy into __constant__ (graph-capturable node)
    void* g_tab_ptr = nullptr;
    cudaGetSymbolAddress(&g_tab_ptr, g_tab);
    cudaMemcpyToSymbolAsync(c_tab, g_tab_ptr, sizeof(float) * TAB_F, 0,
                            cudaMemcpyDeviceToDevice, 0);

    // 3) main kernel
    fk_kernel<<<batch / TPB, TPB>>>(x, out);
}